// round 3
// baseline (speedup 1.0000x reference)
#include <cuda_runtime.h>
#include <math.h>

// Problem constants
#define NROWS 16384
#define INDIM 1024
#define NHEAD 16
#define DEPTH 64            // D = IN/H
#define KDIM 1024
#define NDIM 1024

// SGEMM tiling
#define BM 128
#define BN 128
#define BK 16
#define TM 8
#define TN 8
#define SMPAD 4             // pad leading dim to 132 to reduce STS conflicts

// Scratch: 9 projection buffers + averaged attention output (device globals; no allocs)
__device__ float g_buf[9][(size_t)NROWS * INDIM];
__device__ float g_avg[(size_t)NROWS * INDIM];

// C[m,n] = sum_k A[m,k] * B[n,k] + bias[n]   (both A and B are K-contiguous row-major)
// dst_idx >= 0  -> C = g_buf[dst_idx], else C = Cext
// use_avg_A != 0 -> A = g_avg
__global__ __launch_bounds__(256) void sgemm_nt_kernel(
    const float* __restrict__ Aext, const float* __restrict__ B,
    const float* __restrict__ bias, float* __restrict__ Cext,
    int dst_idx, int use_avg_A, int relu)
{
    const float* __restrict__ A = use_avg_A ? g_avg : Aext;
    float* __restrict__ C = (dst_idx >= 0) ? g_buf[dst_idx] : Cext;

    __shared__ float As[BK][BM + SMPAD];
    __shared__ float Bs[BK][BN + SMPAD];

    const int tid = threadIdx.x;
    const int tx = tid & 15;        // 0..15 -> n microtile
    const int ty = tid >> 4;        // 0..15 -> m microtile

    const size_t m0 = (size_t)blockIdx.y * BM;
    const size_t n0 = (size_t)blockIdx.x * BN;

    // Global->reg staging mapping: 512 float4 per tile, 2 per thread
    const int r0 = tid >> 2;            // 0..63 (row within tile; second load +64)
    const int v0 = (tid & 3) * 4;       // k offset within tile: 0,4,8,12

    const float* __restrict__ Abase = A + m0 * KDIM;
    const float* __restrict__ Bbase = B + n0 * KDIM;

    float acc[TM][TN];
#pragma unroll
    for (int i = 0; i < TM; i++)
#pragma unroll
        for (int j = 0; j < TN; j++) acc[i][j] = 0.0f;

    const int numTiles = KDIM / BK;     // 64

    float4 a_st0, a_st1, b_st0, b_st1;
    // prologue: stage tile 0
    a_st0 = __ldg((const float4*)(Abase + (size_t)r0 * KDIM + v0));
    a_st1 = __ldg((const float4*)(Abase + (size_t)(r0 + 64) * KDIM + v0));
    b_st0 = __ldg((const float4*)(Bbase + (size_t)r0 * KDIM + v0));
    b_st1 = __ldg((const float4*)(Bbase + (size_t)(r0 + 64) * KDIM + v0));

    for (int t = 0; t < numTiles; t++) {
        // commit staged tile to smem (transposed: [k][m])
        As[v0 + 0][r0] = a_st0.x; As[v0 + 1][r0] = a_st0.y;
        As[v0 + 2][r0] = a_st0.z; As[v0 + 3][r0] = a_st0.w;
        As[v0 + 0][r0 + 64] = a_st1.x; As[v0 + 1][r0 + 64] = a_st1.y;
        As[v0 + 2][r0 + 64] = a_st1.z; As[v0 + 3][r0 + 64] = a_st1.w;
        Bs[v0 + 0][r0] = b_st0.x; Bs[v0 + 1][r0] = b_st0.y;
        Bs[v0 + 2][r0] = b_st0.z; Bs[v0 + 3][r0] = b_st0.w;
        Bs[v0 + 0][r0 + 64] = b_st1.x; Bs[v0 + 1][r0 + 64] = b_st1.y;
        Bs[v0 + 2][r0 + 64] = b_st1.z; Bs[v0 + 3][r0 + 64] = b_st1.w;
        __syncthreads();

        // prefetch next tile into registers (overlaps with compute)
        if (t + 1 < numTiles) {
            const int k0 = (t + 1) * BK + v0;
            a_st0 = __ldg((const float4*)(Abase + (size_t)r0 * KDIM + k0));
            a_st1 = __ldg((const float4*)(Abase + (size_t)(r0 + 64) * KDIM + k0));
            b_st0 = __ldg((const float4*)(Bbase + (size_t)r0 * KDIM + k0));
            b_st1 = __ldg((const float4*)(Bbase + (size_t)(r0 + 64) * KDIM + k0));
        }

        // compute on current tile
#pragma unroll
        for (int kk = 0; kk < BK; kk++) {
            float4 a0 = *(const float4*)&As[kk][ty * TM];
            float4 a1 = *(const float4*)&As[kk][ty * TM + 4];
            float4 b0 = *(const float4*)&Bs[kk][tx * TN];
            float4 b1 = *(const float4*)&Bs[kk][tx * TN + 4];
            float av[TM], bv[TN];
            av[0] = a0.x; av[1] = a0.y; av[2] = a0.z; av[3] = a0.w;
            av[4] = a1.x; av[5] = a1.y; av[6] = a1.z; av[7] = a1.w;
            bv[0] = b0.x; bv[1] = b0.y; bv[2] = b0.z; bv[3] = b0.w;
            bv[4] = b1.x; bv[5] = b1.y; bv[6] = b1.z; bv[7] = b1.w;
#pragma unroll
            for (int i = 0; i < TM; i++)
#pragma unroll
                for (int j = 0; j < TN; j++)
                    acc[i][j] = fmaf(av[i], bv[j], acc[i][j]);
        }
        __syncthreads();
    }

    // epilogue: bias (+relu), vectorized stores
    float4 bi0 = *(const float4*)(bias + n0 + tx * TN);
    float4 bi1 = *(const float4*)(bias + n0 + tx * TN + 4);
    float bb[TN];
    bb[0] = bi0.x; bb[1] = bi0.y; bb[2] = bi0.z; bb[3] = bi0.w;
    bb[4] = bi1.x; bb[5] = bi1.y; bb[6] = bi1.z; bb[7] = bi1.w;

#pragma unroll
    for (int i = 0; i < TM; i++) {
        const size_t m = m0 + (size_t)ty * TM + i;
        float out[TN];
#pragma unroll
        for (int j = 0; j < TN; j++) {
            float v = acc[i][j] + bb[j];
            if (relu) v = fmaxf(v, 0.0f);
            out[j] = v;
        }
        float* cp = C + m * NDIM + n0 + tx * TN;
        *(float4*)(cp + 0) = make_float4(out[0], out[1], out[2], out[3]);
        *(float4*)(cp + 4) = make_float4(out[4], out[5], out[6], out[7]);
    }
}

// Per-row attention ×3 + average.
// g_buf layout: [3a+0]=Q_a, [3a+1]=K_a, [3a+2]=V_a.
// Q[d,h] = proj[n*1024 + h*64 + d]; S[d,e] = (1/8) sum_h Q[d,h] K[e,h];
// softmax over d (axis=1!); O[d,h] = sum_e W[d,e] V[e,h];
// avg_out[n*1024 + h*64 + d] = mean over a of O_a[d,h].
__global__ __launch_bounds__(256) void attn_kernel()
{
    const int n = blockIdx.x;
    const int tid = threadIdx.x;

    __shared__ float Qs[DEPTH][NHEAD + 1];
    __shared__ float Ks[DEPTH][NHEAD + 1];
    __shared__ float Vs[DEPTH][NHEAD + 1];
    __shared__ float S[DEPTH][DEPTH + 1];

    float acc[4] = {0.f, 0.f, 0.f, 0.f};

    for (int a = 0; a < 3; a++) {
        const float* __restrict__ Qp = g_buf[3 * a + 0] + (size_t)n * INDIM;
        const float* __restrict__ Kp = g_buf[3 * a + 1] + (size_t)n * INDIM;
        const float* __restrict__ Vp = g_buf[3 * a + 2] + (size_t)n * INDIM;

        // coalesced loads: element c = h*64 + d
#pragma unroll
        for (int j = 0; j < 4; j++) {
            int idx = tid + j * 256;
            int h = idx >> 6, d = idx & 63;
            Qs[d][h] = Qp[idx];
            Ks[d][h] = Kp[idx];
            Vs[d][h] = Vp[idx];
        }
        __syncthreads();

        // scores: each thread computes 16 entries of row d
        {
            int d = tid >> 2;
            int e0 = (tid & 3) * 16;
            float q[NHEAD];
#pragma unroll
            for (int h = 0; h < NHEAD; h++) q[h] = Qs[d][h];
#pragma unroll
            for (int j = 0; j < 16; j++) {
                int e = e0 + j;
                float s = 0.f;
#pragma unroll
                for (int h = 0; h < NHEAD; h++) s = fmaf(q[h], Ks[e][h], s);
                S[d][e] = s * 0.125f;
            }
        }
        __syncthreads();

        // column-wise softmax over d (threads 0..63, one column each)
        if (tid < DEPTH) {
            const int e = tid;
            float mx = -1e30f;
#pragma unroll 8
            for (int d = 0; d < DEPTH; d++) mx = fmaxf(mx, S[d][e]);
            float sum = 0.f;
#pragma unroll 8
            for (int d = 0; d < DEPTH; d++) {
                float ex = expf(S[d][e] - mx);
                S[d][e] = ex;
                sum += ex;
            }
            float inv = 1.0f / sum;
#pragma unroll 8
            for (int d = 0; d < DEPTH; d++) S[d][e] *= inv;
        }
        __syncthreads();

        // O[d,h]: thread handles output elements idx = tid*4 + j, with
        // d = idx & 63, h = idx >> 6  (so final write at offset idx is coalesced)
#pragma unroll
        for (int j = 0; j < 4; j++) {
            int idx = tid * 4 + j;
            int d = idx & 63, h = idx >> 6;
            float o = 0.f;
#pragma unroll 8
            for (int e = 0; e < DEPTH; e++) o = fmaf(S[d][e], Vs[e][h], o);
            acc[j] += o;
        }
        __syncthreads();   // before next attn overwrites smem
    }

    float* op = g_avg + (size_t)n * INDIM + (size_t)tid * 4;
    const float third = 1.0f / 3.0f;
    *(float4*)op = make_float4(acc[0] * third, acc[1] * third,
                               acc[2] * third, acc[3] * third);
}

extern "C" void kernel_launch(void* const* d_in, const int* in_sizes, int n_in,
                              void* d_out, int out_size)
{
    const float* query = (const float*)d_in[0];
    const float* key   = (const float*)d_in[1];
    const float* value = (const float*)d_in[2];
    const float* Wq1 = (const float*)d_in[3];  const float* bq1 = (const float*)d_in[4];
    const float* Wk1 = (const float*)d_in[5];  const float* bk1 = (const float*)d_in[6];
    const float* Wv1 = (const float*)d_in[7];  const float* bv1 = (const float*)d_in[8];
    const float* Wq2 = (const float*)d_in[9];  const float* bq2 = (const float*)d_in[10];
    const float* Wk2 = (const float*)d_in[11]; const float* bk2 = (const float*)d_in[12];
    const float* Wv2 = (const float*)d_in[13]; const float* bv2 = (const float*)d_in[14];
    const float* Wq3 = (const float*)d_in[15]; const float* bq3 = (const float*)d_in[16];
    const float* Wk3 = (const float*)d_in[17]; const float* bk3 = (const float*)d_in[18];
    const float* Wv3 = (const float*)d_in[19]; const float* bv3 = (const float*)d_in[20];
    const float* Wo  = (const float*)d_in[21]; const float* bo  = (const float*)d_in[22];

    dim3 grid(NDIM / BN, NROWS / BM);   // (8, 128)

    // Cross-wired projections (exactly as in the reference):
    //   Q1 = lin(query, Wq1), K1 = lin(value, Wk2), V1 = lin(key,   Wv1)
    //   Q2 = lin(value, Wq2), K2 = lin(key,   Wk1), V2 = lin(query, Wv2)
    //   Q3 = lin(key,   Wq3), K3 = lin(query, Wk3), V3 = lin(value, Wv3)
    struct Job { const float* A; const float* W; const float* b; int dst; };
    const Job jobs[9] = {
        { query, Wq1, bq1, 0 },   // Q1
        { value, Wk2, bk2, 1 },   // K1
        { key,   Wv1, bv1, 2 },   // V1
        { value, Wq2, bq2, 3 },   // Q2
        { key,   Wk1, bk1, 4 },   // K2
        { query, Wv2, bv2, 5 },   // V2
        { key,   Wq3, bq3, 6 },   // Q3
        { query, Wk3, bk3, 7 },   // K3
        { value, Wv3, bv3, 8 },   // V3
    };

    for (int i = 0; i < 9; i++) {
        sgemm_nt_kernel<<<grid, 256>>>(jobs[i].A, jobs[i].W, jobs[i].b,
                                       nullptr, jobs[i].dst, 0, 0);
    }

    attn_kernel<<<NROWS, 256>>>();

    // out = relu(avg @ Wo^T + bo)
    sgemm_nt_kernel<<<grid, 256>>>(nullptr, Wo, bo, (float*)d_out, -1, 1, 1);
}

// round 10
// speedup vs baseline: 1.7805x; 1.7805x over previous
#include <cuda_runtime.h>
#include <cuda_bf16.h>
#include <stdint.h>
#include <math.h>

// Problem constants
#define NROWS 16384
#define INDIM 1024
#define NHEAD 16
#define DEPTH 64
#define KDIM 1024
#define NDIM 1024

// GEMM tiling
#define BM 128
#define BN 128
#define BK 32
#define SPITCH 40            // smem row pitch in bf16 elems (80B) -> LDSM conflict-free

// ---------------- device scratch ----------------
// act splits: 0=query 1=key 2=value 3=avg
__device__ __nv_bfloat16 g_act_hi[4][(size_t)NROWS * INDIM];
__device__ __nv_bfloat16 g_act_lo[4][(size_t)NROWS * INDIM];
__device__ __nv_bfloat16 g_w_hi[10][(size_t)INDIM * INDIM];
__device__ __nv_bfloat16 g_w_lo[10][(size_t)INDIM * INDIM];
__device__ float g_buf[9][(size_t)NROWS * INDIM];

__device__ __forceinline__ uint32_t smem_to_u32(const void* p) {
    uint32_t a;
    asm("{ .reg .u64 t; cvta.to.shared.u64 t, %1; cvt.u32.u64 %0, t; }" : "=r"(a) : "l"(p));
    return a;
}
__device__ __forceinline__ void ldsm_x4(uint32_t* r, uint32_t addr) {
    asm volatile("ldmatrix.sync.aligned.m8n8.x4.shared.b16 {%0,%1,%2,%3}, [%4];"
                 : "=r"(r[0]), "=r"(r[1]), "=r"(r[2]), "=r"(r[3]) : "r"(addr));
}
__device__ __forceinline__ void mma16816(float* d, const uint32_t* a, const uint32_t* b) {
    asm volatile(
        "mma.sync.aligned.m16n8k16.row.col.f32.bf16.bf16.f32 "
        "{%0,%1,%2,%3}, {%4,%5,%6,%7}, {%8,%9}, {%0,%1,%2,%3};"
        : "+f"(d[0]), "+f"(d[1]), "+f"(d[2]), "+f"(d[3])
        : "r"(a[0]), "r"(a[1]), "r"(a[2]), "r"(a[3]), "r"(b[0]), "r"(b[1]));
}

// ---------------- fp32 -> bf16 hi/lo split (external sources) ----------------
__global__ __launch_bounds__(256) void cvt_kernel(const float* __restrict__ src,
                                                  int kind, int idx, int n)
{
    __nv_bfloat16* __restrict__ hi = kind ? g_w_hi[idx] : g_act_hi[idx];
    __nv_bfloat16* __restrict__ lo = kind ? g_w_lo[idx] : g_act_lo[idx];
    int i = (blockIdx.x * 256 + threadIdx.x) * 4;
    if (i >= n) return;
    float4 v = *(const float4*)(src + i);
    float f[4] = {v.x, v.y, v.z, v.w};
    __nv_bfloat16 h[4], l[4];
#pragma unroll
    for (int j = 0; j < 4; j++) {
        h[j] = __float2bfloat16_rn(f[j]);
        l[j] = __float2bfloat16_rn(f[j] - __bfloat162float(h[j]));
    }
    __nv_bfloat162* hp = (__nv_bfloat162*)(hi + i);
    __nv_bfloat162* lp = (__nv_bfloat162*)(lo + i);
    hp[0] = __nv_bfloat162(h[0], h[1]); hp[1] = __nv_bfloat162(h[2], h[3]);
    lp[0] = __nv_bfloat162(l[0], l[1]); lp[1] = __nv_bfloat162(l[2], l[3]);
}

// average O1,O2,O3 (in g_buf[0],[3],[6]) and split into g_act_hi/lo[3]
__global__ __launch_bounds__(256) void avg_cvt_kernel()
{
    int i = (blockIdx.x * 256 + threadIdx.x) * 4;
    float4 a = *(const float4*)(g_buf[0] + i);
    float4 b = *(const float4*)(g_buf[3] + i);
    float4 c = *(const float4*)(g_buf[6] + i);
    const float third = 1.0f / 3.0f;
    float f[4] = {(a.x + b.x + c.x) * third, (a.y + b.y + c.y) * third,
                  (a.z + b.z + c.z) * third, (a.w + b.w + c.w) * third};
    __nv_bfloat16 h[4], l[4];
#pragma unroll
    for (int j = 0; j < 4; j++) {
        h[j] = __float2bfloat16_rn(f[j]);
        l[j] = __float2bfloat16_rn(f[j] - __bfloat162float(h[j]));
    }
    __nv_bfloat162* hp = (__nv_bfloat162*)(g_act_hi[3] + i);
    __nv_bfloat162* lp = (__nv_bfloat162*)(g_act_lo[3] + i);
    hp[0] = __nv_bfloat162(h[0], h[1]); hp[1] = __nv_bfloat162(h[2], h[3]);
    lp[0] = __nv_bfloat162(l[0], l[1]); lp[1] = __nv_bfloat162(l[2], l[3]);
}

// ---------------- mma.sync bf16-split GEMM ----------------
// C[m,n] = sum_k A[m,k]*B[n,k] + bias[n]; C += Ahi*Bhi + Ahi*Blo + Alo*Bhi
struct GArgs {
    const float* bias[10];
    float* outC;
};

__global__ __launch_bounds__(256, 1) void gemm_mma_kernel(GArgs ga, int job_base, int relu)
{
    __shared__ __nv_bfloat16 sAh[BM * SPITCH];
    __shared__ __nv_bfloat16 sAl[BM * SPITCH];
    __shared__ __nv_bfloat16 sBh[BN * SPITCH];
    __shared__ __nv_bfloat16 sBl[BN * SPITCH];

    const int job = job_base + (int)blockIdx.z;
    const int map_a[10] = {0, 2, 1, 2, 1, 0, 1, 0, 2, 3};
    const int ai = map_a[job];
    float* __restrict__ C = (job < 9) ? g_buf[job] : ga.outC;
    const float* __restrict__ bias = ga.bias[job];

    const int tid = threadIdx.x;
    const int wid = tid >> 5;
    const int lid = tid & 31;
    const int wm = wid & 3;          // warp m group: rows wm*32
    const int wn = wid >> 2;         // warp n group: cols wn*64
    const size_t m0 = (size_t)blockIdx.y * BM;
    const size_t n0 = (size_t)blockIdx.x * BN;

    // global pointers (K-contiguous rows)
    const __nv_bfloat16* __restrict__ gp[4] = {
        g_act_hi[ai] + m0 * KDIM, g_act_lo[ai] + m0 * KDIM,
        g_w_hi[job]  + n0 * KDIM, g_w_lo[job]  + n0 * KDIM };
    __nv_bfloat16* const sp[4] = {sAh, sAl, sBh, sBl};

    // staging mapping: 128 rows x 4 uint4 per matrix; thread -> row=tid>>1, 2 uint4
    const int r = tid >> 1;
    const int cp = (tid & 1) * 2;     // uint4 index (0 or 2), loads cp and cp+1

    float acc[2][8][4];
#pragma unroll
    for (int a = 0; a < 2; a++)
#pragma unroll
        for (int b = 0; b < 8; b++)
#pragma unroll
            for (int c = 0; c < 4; c++) acc[a][b][c] = 0.0f;

    // ldmatrix base addresses (bytes)
    const uint32_t uAh = smem_to_u32(sAh), uAl = smem_to_u32(sAl);
    const uint32_t uBh = smem_to_u32(sBh), uBl = smem_to_u32(sBl);
    // A x4: lanes 0-15 rows 0-15 colbyte+0, lanes 16-31 rows 0-15 colbyte+16
    const uint32_t aRow = (uint32_t)(wm * 32 + (lid & 15));
    const uint32_t aCol = (uint32_t)((lid >> 4) << 4);
    // B x4: lanes 0-7 rows0-7 c0, 8-15 rows0-7 c16, 16-23 rows8-15 c0, 24-31 rows8-15 c16
    const uint32_t bRow = (uint32_t)(wn * 64 + (lid & 7) + ((lid >> 4) << 3));
    const uint32_t bCol = (uint32_t)(((lid >> 3) & 1) << 4);

    const int NCH = KDIM / BK;        // 32
    uint4 st[4][2];

    // prologue: stage chunk 0
#pragma unroll
    for (int x = 0; x < 4; x++) {
        st[x][0] = *(const uint4*)(gp[x] + (size_t)r * KDIM + (cp + 0) * 8);
        st[x][1] = *(const uint4*)(gp[x] + (size_t)r * KDIM + (cp + 1) * 8);
    }

    for (int t = 0; t < NCH; t++) {
        // commit staged chunk to smem
#pragma unroll
        for (int x = 0; x < 4; x++) {
            *(uint4*)(sp[x] + r * SPITCH + (cp + 0) * 8) = st[x][0];
            *(uint4*)(sp[x] + r * SPITCH + (cp + 1) * 8) = st[x][1];
        }
        __syncthreads();

        // prefetch next chunk into registers
        if (t + 1 < NCH) {
            const int ke = (t + 1) * BK;
#pragma unroll
            for (int x = 0; x < 4; x++) {
                st[x][0] = *(const uint4*)(gp[x] + (size_t)r * KDIM + ke + (cp + 0) * 8);
                st[x][1] = *(const uint4*)(gp[x] + (size_t)r * KDIM + ke + (cp + 1) * 8);
            }
        }

        // compute: 2 k16 steps
#pragma unroll
        for (int kk = 0; kk < 2; kk++) {
            const uint32_t kb = (uint32_t)(kk * 32);
            uint32_t afh[2][4], afl[2][4];
#pragma unroll
            for (int mt = 0; mt < 2; mt++) {
                const uint32_t ao = (aRow + mt * 16) * (SPITCH * 2) + kb + aCol;
                ldsm_x4(afh[mt], uAh + ao);
                ldsm_x4(afl[mt], uAl + ao);
            }
#pragma unroll
            for (int p = 0; p < 4; p++) {
                uint32_t bfh[4], bfl[4];
                const uint32_t bo = (bRow + p * 16) * (SPITCH * 2) + kb + bCol;
                ldsm_x4(bfh, uBh + bo);
                ldsm_x4(bfl, uBl + bo);
#pragma unroll
                for (int mt = 0; mt < 2; mt++) {
                    mma16816(acc[mt][2 * p + 0], afh[mt], bfh + 0);
                    mma16816(acc[mt][2 * p + 0], afh[mt], bfl + 0);
                    mma16816(acc[mt][2 * p + 0], afl[mt], bfh + 0);
                    mma16816(acc[mt][2 * p + 1], afh[mt], bfh + 2);
                    mma16816(acc[mt][2 * p + 1], afh[mt], bfl + 2);
                    mma16816(acc[mt][2 * p + 1], afl[mt], bfh + 2);
                }
            }
        }
        __syncthreads();
    }

    // epilogue: accum frag -> C with bias (+relu)
    const int grp = lid >> 2;
    const int qd = lid & 3;
#pragma unroll
    for (int mt = 0; mt < 2; mt++) {
        const size_t row0 = m0 + wm * 32 + mt * 16 + grp;
        const size_t row1 = row0 + 8;
#pragma unroll
        for (int nt = 0; nt < 8; nt++) {
            const size_t col = n0 + wn * 64 + nt * 8 + qd * 2;
            float2 v0, v1;
            v0.x = acc[mt][nt][0] + bias[col];
            v0.y = acc[mt][nt][1] + bias[col + 1];
            v1.x = acc[mt][nt][2] + bias[col];
            v1.y = acc[mt][nt][3] + bias[col + 1];
            if (relu) {
                v0.x = fmaxf(v0.x, 0.f); v0.y = fmaxf(v0.y, 0.f);
                v1.x = fmaxf(v1.x, 0.f); v1.y = fmaxf(v1.y, 0.f);
            }
            *(float2*)(C + row0 * NDIM + col) = v0;
            *(float2*)(C + row1 * NDIM + col) = v1;
        }
    }
}

// ---------------- per-(row, attention) kernel ----------------
// block (n, a): computes O_a for row n, writes in-place to g_buf[3a] row n.
__global__ __launch_bounds__(256) void attn_kernel()
{
    const int n = blockIdx.x;
    const int a = (int)blockIdx.y;
    const int tid = threadIdx.x;

    __shared__ float Qs[DEPTH][NHEAD + 1];
    __shared__ float Ks[DEPTH][NHEAD + 1];
    __shared__ float Vs[DEPTH][NHEAD + 1];
    __shared__ float S[DEPTH][DEPTH + 1];

    const float* __restrict__ Qp = g_buf[3 * a + 0] + (size_t)n * INDIM;
    const float* __restrict__ Kp = g_buf[3 * a + 1] + (size_t)n * INDIM;
    const float* __restrict__ Vp = g_buf[3 * a + 2] + (size_t)n * INDIM;

#pragma unroll
    for (int j = 0; j < 4; j++) {
        int idx = tid + j * 256;
        int h = idx >> 6, d = idx & 63;
        Qs[d][h] = Qp[idx];
        Ks[d][h] = Kp[idx];
        Vs[d][h] = Vp[idx];
    }
    __syncthreads();

    // scores: thread computes 16 entries of row d
    {
        int d = tid >> 2;
        int e0 = (tid & 3) * 16;
        float q[NHEAD];
#pragma unroll
        for (int h = 0; h < NHEAD; h++) q[h] = Qs[d][h];
#pragma unroll
        for (int j = 0; j < 16; j++) {
            int e = e0 + j;
            float s = 0.f;
#pragma unroll
            for (int h = 0; h < NHEAD; h++) s = fmaf(q[h], Ks[e][h], s);
            S[d][e] = s * 0.125f;
        }
    }
    __syncthreads();

    // column-wise softmax over d (axis=1)
    if (tid < DEPTH) {
        const int e = tid;
        float mx = -1e30f;
#pragma unroll 8
        for (int d = 0; d < DEPTH; d++) mx = fmaxf(mx, S[d][e]);
        float sum = 0.f;
#pragma unroll 8
        for (int d = 0; d < DEPTH; d++) {
            float ex = expf(S[d][e] - mx);
            S[d][e] = ex;
            sum += ex;
        }
        float inv = 1.0f / sum;
#pragma unroll 8
        for (int d = 0; d < DEPTH; d++) S[d][e] *= inv;
    }
    __syncthreads();

    // O[d,h] -> write in-place to g_buf[3a] row n (coalesced)
    float out[4];
#pragma unroll
    for (int j = 0; j < 4; j++) {
        int idx = tid * 4 + j;
        int d = idx & 63, h = idx >> 6;
        float o = 0.f;
#pragma unroll 8
        for (int e = 0; e < DEPTH; e++) o = fmaf(S[d][e], Vs[e][h], o);
        out[j] = o;
    }
    float* op = g_buf[3 * a + 0] + (size_t)n * INDIM + (size_t)tid * 4;
    *(float4*)op = make_float4(out[0], out[1], out[2], out[3]);
}

// ---------------- launch ----------------
extern "C" void kernel_launch(void* const* d_in, const int* in_sizes, int n_in,
                              void* d_out, int out_size)
{
    const float* query = (const float*)d_in[0];
    const float* key   = (const float*)d_in[1];
    const float* value = (const float*)d_in[2];
    const float* Wq1 = (const float*)d_in[3];  const float* bq1 = (const float*)d_in[4];
    const float* Wk1 = (const float*)d_in[5];  const float* bk1 = (const float*)d_in[6];
    const float* Wv1 = (const float*)d_in[7];  const float* bv1 = (const float*)d_in[8];
    const float* Wq2 = (const float*)d_in[9];  const float* bq2 = (const float*)d_in[10];
    const float* Wk2 = (const float*)d_in[11]; const float* bk2 = (const float*)d_in[12];
    const float* Wv2 = (const float*)d_in[13]; const float* bv2 = (const float*)d_in[14];
    const float* Wq3 = (const float*)d_in[15]; const float* bq3 = (const float*)d_in[16];
    const float* Wk3 = (const float*)d_in[17]; const float* bk3 = (const float*)d_in[18];
    const float* Wv3 = (const float*)d_in[19]; const float* bv3 = (const float*)d_in[20];
    const float* Wo  = (const float*)d_in[21]; const float* bo  = (const float*)d_in[22];

    // activation splits: 0=query 1=key 2=value
    const int nact = NROWS * INDIM;
    const int act_grid = nact / (256 * 4);
    cvt_kernel<<<act_grid, 256>>>(query, 0, 0, nact);
    cvt_kernel<<<act_grid, 256>>>(key,   0, 1, nact);
    cvt_kernel<<<act_grid, 256>>>(value, 0, 2, nact);

    // weight splits in job order (jobs 0..8 -> g_buf[0..8] = Q1,K1,V1,Q2,K2,V2,Q3,K3,V3):
    //   Q1=lin(query,Wq1) K1=lin(value,Wk2) V1=lin(key,Wv1)
    //   Q2=lin(value,Wq2) K2=lin(key,Wk1)   V2=lin(query,Wv2)
    //   Q3=lin(key,Wq3)   K3=lin(query,Wk3) V3=lin(value,Wv3)
    const float* Wjob[10] = {Wq1, Wk2, Wv1, Wq2, Wk1, Wv2, Wq3, Wk3, Wv3, Wo};
    const float* bjob[10] = {bq1, bk2, bv1, bq2, bk1, bv2, bq3, bk3, bv3, bo};
    const int nw = INDIM * INDIM;
    const int w_grid = nw / (256 * 4);
    for (int j = 0; j < 10; j++)
        cvt_kernel<<<w_grid, 256>>>(Wjob[j], 1, j, nw);

    GArgs ga;
    for (int j = 0; j < 10; j++) ga.bias[j] = bjob[j];
    ga.outC = (float*)d_out;

    // 9 projection GEMMs fused in one launch
    dim3 pgrid(NDIM / BN, NROWS / BM, 9);
    gemm_mma_kernel<<<pgrid, 256>>>(ga, 0, 0);

    // attention: one block per (row, attention)
    dim3 agrid(NROWS, 3);
    attn_kernel<<<agrid, 256>>>();

    // fused average + hi/lo split
    avg_cvt_kernel<<<act_grid, 256>>>();

    // final GEMM with ReLU into d_out
    dim3 fgrid(NDIM / BN, NROWS / BM, 1);
    gemm_mma_kernel<<<fgrid, 256>>>(ga, 9, 1);
}